// round 1
// baseline (speedup 1.0000x reference)
#include <cuda_runtime.h>
#include <cstdint>
#include <cstddef>

// Problem constants
#define Bn 4096
#define Dn 512
#define Hn 16
#define HD 8192   // H*D

// ---------------------------------------------------------------------------
// Scratch (device globals — no allocation allowed)
// ---------------------------------------------------------------------------
__device__ float g_K [(size_t)Bn * HD];   // z_query @ Wk
__device__ float g_kw[(size_t)Bn * HD];   // (z_state @ Wk) * lam_m  (row-scaled)
__device__ float g_vw[(size_t)Bn * HD];   // z_value @ Wv
__device__ float g_vm[(size_t)Bn * Dn];   // mean_h(K_h @ M_h)
__device__ float g_lam[Bn];
__device__ float g_inv;                   // 1 / (mask.sum() + 1e-6)

// ---------------------------------------------------------------------------
// Prep: lam_m = clip(1-conf,0,1) * (lam > 0.3);  g_inv = 1/(sum(mask)+1e-6)
// ---------------------------------------------------------------------------
__global__ void prep_kernel(const float* __restrict__ conf) {
    __shared__ float red[256];
    int tid = threadIdx.x;
    float cnt = 0.f;
    for (int b = tid; b < Bn; b += 256) {
        float lam = 1.0f - conf[b];
        lam = fminf(fmaxf(lam, 0.0f), 1.0f);
        float m = (lam > 0.3f) ? 1.0f : 0.0f;
        g_lam[b] = lam * m;
        cnt += m;
    }
    red[tid] = cnt;
    __syncthreads();
    for (int s = 128; s > 0; s >>= 1) {
        if (tid < s) red[tid] += red[tid + s];
        __syncthreads();
    }
    if (tid == 0) g_inv = 1.0f / (red[0] + 1e-6f);
}

// ---------------------------------------------------------------------------
// SGEMM NN:  C[M,N] = alpha * rowscale[m] * (A[M,K] @ B[K,N])
// Tiles: 128x128x8, 256 threads, 8x8 microtile per thread.
// ---------------------------------------------------------------------------
#define BM 128
#define BN 128
#define BK 8
#define TM 8
#define TN 8

__global__ __launch_bounds__(256, 2)
void sgemm_nn(const float* __restrict__ A, const float* __restrict__ B,
              float* __restrict__ C, int M, int N, int K,
              float alpha, const float* __restrict__ rowscale) {
    __shared__ float As[BK][BM + 4];   // transposed, padded vs store conflicts
    __shared__ float Bs[BK][BN];

    const int tid = threadIdx.x;
    const int tx = tid & 15;           // 0..15 -> N direction
    const int ty = tid >> 4;           // 0..15 -> M direction
    const int m0 = blockIdx.y * BM;
    const int n0 = blockIdx.x * BN;

    // A tile loaders: 128 rows x 8 cols = 256 float4
    const int arow = tid >> 1;
    const int acol = (tid & 1) * 4;
    // B tile loaders: 8 rows x 128 cols = 256 float4
    const int brow = tid >> 5;
    const int bcol = (tid & 31) * 4;

    const float* Ap = A + (size_t)(m0 + arow) * K + acol;
    const float* Bp = B + (size_t)brow * N + n0 + bcol;

    float acc[TM][TN];
    #pragma unroll
    for (int i = 0; i < TM; i++)
        #pragma unroll
        for (int j = 0; j < TN; j++) acc[i][j] = 0.f;

    for (int k0 = 0; k0 < K; k0 += BK) {
        float4 av = *(const float4*)Ap;
        float4 bv = *(const float4*)Bp;
        As[acol + 0][arow] = av.x;
        As[acol + 1][arow] = av.y;
        As[acol + 2][arow] = av.z;
        As[acol + 3][arow] = av.w;
        *(float4*)(&Bs[brow][bcol]) = bv;
        __syncthreads();

        #pragma unroll
        for (int kk = 0; kk < BK; kk++) {
            float a[TM], b[TN];
            #pragma unroll
            for (int i = 0; i < TM; i += 4)
                *(float4*)&a[i] = *(const float4*)&As[kk][ty * TM + i];
            #pragma unroll
            for (int j = 0; j < TN; j += 4)
                *(float4*)&b[j] = *(const float4*)&Bs[kk][tx * TN + j];
            #pragma unroll
            for (int i = 0; i < TM; i++)
                #pragma unroll
                for (int j = 0; j < TN; j++)
                    acc[i][j] = fmaf(a[i], b[j], acc[i][j]);
        }
        __syncthreads();
        Ap += BK;
        Bp += (size_t)BK * N;
    }

    #pragma unroll
    for (int i = 0; i < TM; i++) {
        const int m = m0 + ty * TM + i;
        float rs = alpha;
        if (rowscale) rs *= rowscale[m];
        float* crow = C + (size_t)m * N + n0 + tx * TN;
        #pragma unroll
        for (int j = 0; j < TN; j += 4) {
            float4 v;
            v.x = acc[i][j + 0] * rs;
            v.y = acc[i][j + 1] * rs;
            v.z = acc[i][j + 2] * rs;
            v.w = acc[i][j + 3] * rs;
            *(float4*)(crow + j) = v;
        }
    }
}

// ---------------------------------------------------------------------------
// Delta: per head h,  Out_h[m,n] = Mem_h[m,n] + g_inv * sum_b kw[b,hD+m]*vw[b,hD+n]
// A^T @ B with both operands row-major in the batch dim (K-major tiles — no
// transpose needed on load). M=N=512, Kdim=4096, lda=ldb=8192.
// ---------------------------------------------------------------------------
__global__ __launch_bounds__(256, 2)
void sgemm_atb_delta(const float* __restrict__ Kw, const float* __restrict__ Vw,
                     const float* __restrict__ Mem, float* __restrict__ Out) {
    __shared__ float As[BK][BM];
    __shared__ float Bs[BK][BN];

    const int tid = threadIdx.x;
    const int tx = tid & 15;
    const int ty = tid >> 4;
    const int h  = blockIdx.z;
    const int m0 = blockIdx.y * BM;
    const int n0 = blockIdx.x * BN;

    const float* A = Kw + (size_t)h * Dn;   // A[k, m] at A[k*HD + m]
    const float* B = Vw + (size_t)h * Dn;

    const int lrow = tid >> 5;              // 0..7 (k within tile)
    const int lcol = (tid & 31) * 4;        // 0..124

    const float* Ap = A + (size_t)lrow * HD + m0 + lcol;
    const float* Bp = B + (size_t)lrow * HD + n0 + lcol;

    float acc[TM][TN];
    #pragma unroll
    for (int i = 0; i < TM; i++)
        #pragma unroll
        for (int j = 0; j < TN; j++) acc[i][j] = 0.f;

    for (int k0 = 0; k0 < Bn; k0 += BK) {
        *(float4*)(&As[lrow][lcol]) = *(const float4*)Ap;
        *(float4*)(&Bs[lrow][lcol]) = *(const float4*)Bp;
        __syncthreads();

        #pragma unroll
        for (int kk = 0; kk < BK; kk++) {
            float a[TM], b[TN];
            #pragma unroll
            for (int i = 0; i < TM; i += 4)
                *(float4*)&a[i] = *(const float4*)&As[kk][ty * TM + i];
            #pragma unroll
            for (int j = 0; j < TN; j += 4)
                *(float4*)&b[j] = *(const float4*)&Bs[kk][tx * TN + j];
            #pragma unroll
            for (int i = 0; i < TM; i++)
                #pragma unroll
                for (int j = 0; j < TN; j++)
                    acc[i][j] = fmaf(a[i], b[j], acc[i][j]);
        }
        __syncthreads();
        Ap += (size_t)BK * HD;
        Bp += (size_t)BK * HD;
    }

    const float inv = g_inv;
    #pragma unroll
    for (int i = 0; i < TM; i++) {
        const int m = m0 + ty * TM + i;
        const size_t base = (size_t)h * Dn * Dn + (size_t)m * Dn + n0 + tx * TN;
        #pragma unroll
        for (int j = 0; j < TN; j += 4) {
            float4 mm = *(const float4*)(Mem + base + j);
            float4 v;
            v.x = mm.x + acc[i][j + 0] * inv;
            v.y = mm.y + acc[i][j + 1] * inv;
            v.z = mm.z + acc[i][j + 2] * inv;
            v.w = mm.w + acc[i][j + 3] * inv;
            *(float4*)(Out + base + j) = v;
        }
    }
}

// ---------------------------------------------------------------------------
// Launch
// ---------------------------------------------------------------------------
extern "C" void kernel_launch(void* const* d_in, const int* in_sizes, int n_in,
                              void* d_out, int out_size) {
    const float* z_query    = (const float*)d_in[0];
    const float* z_state    = (const float*)d_in[1];
    const float* z_value    = (const float*)d_in[2];
    const float* confidence = (const float*)d_in[3];
    const float* Wk         = (const float*)d_in[4];
    const float* Wv         = (const float*)d_in[5];
    const float* Wo         = (const float*)d_in[6];
    const float* memory     = (const float*)d_in[7];

    float* out_vret = (float*)d_out;                         // (B, D)
    float* out_mem  = (float*)d_out + (size_t)Bn * Dn;       // (H, D, D)

    float *pK, *pKw, *pVw, *pVm;
    cudaGetSymbolAddress((void**)&pK,  g_K);
    cudaGetSymbolAddress((void**)&pKw, g_kw);
    cudaGetSymbolAddress((void**)&pVw, g_vw);
    cudaGetSymbolAddress((void**)&pVm, g_vm);
    float* pLam;
    cudaGetSymbolAddress((void**)&pLam, g_lam);

    // 1. lam_m + mask-sum
    prep_kernel<<<1, 256>>>(confidence);

    // 2. K = z_query @ Wk                      (4096 x 8192, K=512)
    sgemm_nn<<<dim3(HD / BN, Bn / BM), 256>>>(z_query, Wk, pK, Bn, HD, Dn, 1.0f, nullptr);

    // 3. vmean = (1/H) * K @ memory.reshape(8192,512)   (4096 x 512, K=8192)
    sgemm_nn<<<dim3(Dn / BN, Bn / BM), 256>>>(pK, memory, pVm, Bn, Dn, HD, 1.0f / Hn, nullptr);

    // 4. v_ret = vmean @ Wo -> d_out           (4096 x 512, K=512)
    sgemm_nn<<<dim3(Dn / BN, Bn / BM), 256>>>(pVm, Wo, out_vret, Bn, Dn, Dn, 1.0f, nullptr);

    // 5. kw_scaled = (z_state @ Wk) * lam_m[row]   (4096 x 8192, K=512)
    sgemm_nn<<<dim3(HD / BN, Bn / BM), 256>>>(z_state, Wk, pKw, Bn, HD, Dn, 1.0f, pLam);

    // 6. vw = z_value @ Wv                     (4096 x 8192, K=512)
    sgemm_nn<<<dim3(HD / BN, Bn / BM), 256>>>(z_value, Wv, pVw, Bn, HD, Dn, 1.0f, nullptr);

    // 7. new_memory = memory + (kw_h^T @ vw_h) * g_inv  per head
    sgemm_atb_delta<<<dim3(Dn / BN, Dn / BM, Hn), 256>>>(pKw, pVw, memory, out_mem);
}

// round 2
// speedup vs baseline: 1.0452x; 1.0452x over previous
#include <cuda_runtime.h>
#include <cstdint>
#include <cstddef>

// Problem constants
#define Bn 4096
#define Dn 512
#define Hn 16
#define HD 8192   // H*D

// ---------------------------------------------------------------------------
// Scratch (device globals — no allocation allowed)
// ---------------------------------------------------------------------------
__device__ float g_K [(size_t)Bn * HD];   // z_query @ Wk
__device__ float g_kw[(size_t)Bn * HD];   // (z_state @ Wk) * lam_m  (row-scaled)
__device__ float g_vw[(size_t)Bn * HD];   // z_value @ Wv
__device__ float g_vm[(size_t)Bn * Dn];   // mean_h(K_h @ M_h)
__device__ float g_lam[Bn];
__device__ float g_inv;                   // 1 / (mask.sum() + 1e-6)

// ---------------------------------------------------------------------------
// Prep: lam_m = clip(1-conf,0,1) * (lam > 0.3);  g_inv = 1/(sum(mask)+1e-6)
// ---------------------------------------------------------------------------
__global__ void prep_kernel(const float* __restrict__ conf) {
    __shared__ float red[256];
    int tid = threadIdx.x;
    float cnt = 0.f;
    for (int b = tid; b < Bn; b += 256) {
        float lam = 1.0f - conf[b];
        lam = fminf(fmaxf(lam, 0.0f), 1.0f);
        float m = (lam > 0.3f) ? 1.0f : 0.0f;
        g_lam[b] = lam * m;
        cnt += m;
    }
    red[tid] = cnt;
    __syncthreads();
    for (int s = 128; s > 0; s >>= 1) {
        if (tid < s) red[tid] += red[tid + s];
        __syncthreads();
    }
    if (tid == 0) g_inv = 1.0f / (red[0] + 1e-6f);
}

// ---------------------------------------------------------------------------
// SGEMM NN:  C[M,N] = alpha * rowscale[m] * (A[M,K] @ B[K,N])
// Tiles: 128x128x8, 256 threads, 8x8 microtile per thread.
// ---------------------------------------------------------------------------
#define BM 128
#define BN 128
#define BK 8
#define TM 8
#define TN 8

__global__ __launch_bounds__(256, 2)
void sgemm_nn(const float* __restrict__ A, const float* __restrict__ B,
              float* __restrict__ C, int M, int N, int K,
              float alpha, const float* __restrict__ rowscale) {
    __shared__ float As[BK][BM + 4];   // transposed, padded vs store conflicts
    __shared__ float Bs[BK][BN];

    const int tid = threadIdx.x;
    const int tx = tid & 15;           // 0..15 -> N direction
    const int ty = tid >> 4;           // 0..15 -> M direction
    const int m0 = blockIdx.y * BM;
    const int n0 = blockIdx.x * BN;

    // A tile loaders: 128 rows x 8 cols = 256 float4
    const int arow = tid >> 1;
    const int acol = (tid & 1) * 4;
    // B tile loaders: 8 rows x 128 cols = 256 float4
    const int brow = tid >> 5;
    const int bcol = (tid & 31) * 4;

    const float* Ap = A + (size_t)(m0 + arow) * K + acol;
    const float* Bp = B + (size_t)brow * N + n0 + bcol;

    float acc[TM][TN];
    #pragma unroll
    for (int i = 0; i < TM; i++)
        #pragma unroll
        for (int j = 0; j < TN; j++) acc[i][j] = 0.f;

    for (int k0 = 0; k0 < K; k0 += BK) {
        float4 av = *(const float4*)Ap;
        float4 bv = *(const float4*)Bp;
        As[acol + 0][arow] = av.x;
        As[acol + 1][arow] = av.y;
        As[acol + 2][arow] = av.z;
        As[acol + 3][arow] = av.w;
        *(float4*)(&Bs[brow][bcol]) = bv;
        __syncthreads();

        #pragma unroll
        for (int kk = 0; kk < BK; kk++) {
            float a[TM], b[TN];
            #pragma unroll
            for (int i = 0; i < TM; i += 4)
                *(float4*)&a[i] = *(const float4*)&As[kk][ty * TM + i];
            #pragma unroll
            for (int j = 0; j < TN; j += 4)
                *(float4*)&b[j] = *(const float4*)&Bs[kk][tx * TN + j];
            #pragma unroll
            for (int i = 0; i < TM; i++)
                #pragma unroll
                for (int j = 0; j < TN; j++)
                    acc[i][j] = fmaf(a[i], b[j], acc[i][j]);
        }
        __syncthreads();
        Ap += BK;
        Bp += (size_t)BK * N;
    }

    #pragma unroll
    for (int i = 0; i < TM; i++) {
        const int m = m0 + ty * TM + i;
        float rs = alpha;
        if (rowscale) rs *= rowscale[m];
        float* crow = C + (size_t)m * N + n0 + tx * TN;
        #pragma unroll
        for (int j = 0; j < TN; j += 4) {
            float4 v;
            v.x = acc[i][j + 0] * rs;
            v.y = acc[i][j + 1] * rs;
            v.z = acc[i][j + 2] * rs;
            v.w = acc[i][j + 3] * rs;
            *(float4*)(crow + j) = v;
        }
    }
}

// ---------------------------------------------------------------------------
// Delta: per head h,  Out_h[m,n] = Mem_h[m,n] + g_inv * sum_b kw[b,hD+m]*vw[b,hD+n]
// A^T @ B with both operands row-major in the batch dim (K-major tiles — no
// transpose needed on load). M=N=512, Kdim=4096, lda=ldb=8192.
// ---------------------------------------------------------------------------
__global__ __launch_bounds__(256, 2)
void sgemm_atb_delta(const float* __restrict__ Kw, const float* __restrict__ Vw,
                     const float* __restrict__ Mem, float* __restrict__ Out) {
    __shared__ float As[BK][BM];
    __shared__ float Bs[BK][BN];

    const int tid = threadIdx.x;
    const int tx = tid & 15;
    const int ty = tid >> 4;
    const int h  = blockIdx.z;
    const int m0 = blockIdx.y * BM;
    const int n0 = blockIdx.x * BN;

    const float* A = Kw + (size_t)h * Dn;   // A[k, m] at A[k*HD + m]
    const float* B = Vw + (size_t)h * Dn;

    const int lrow = tid >> 5;              // 0..7 (k within tile)
    const int lcol = (tid & 31) * 4;        // 0..124

    const float* Ap = A + (size_t)lrow * HD + m0 + lcol;
    const float* Bp = B + (size_t)lrow * HD + n0 + lcol;

    float acc[TM][TN];
    #pragma unroll
    for (int i = 0; i < TM; i++)
        #pragma unroll
        for (int j = 0; j < TN; j++) acc[i][j] = 0.f;

    for (int k0 = 0; k0 < Bn; k0 += BK) {
        *(float4*)(&As[lrow][lcol]) = *(const float4*)Ap;
        *(float4*)(&Bs[lrow][lcol]) = *(const float4*)Bp;
        __syncthreads();

        #pragma unroll
        for (int kk = 0; kk < BK; kk++) {
            float a[TM], b[TN];
            #pragma unroll
            for (int i = 0; i < TM; i += 4)
                *(float4*)&a[i] = *(const float4*)&As[kk][ty * TM + i];
            #pragma unroll
            for (int j = 0; j < TN; j += 4)
                *(float4*)&b[j] = *(const float4*)&Bs[kk][tx * TN + j];
            #pragma unroll
            for (int i = 0; i < TM; i++)
                #pragma unroll
                for (int j = 0; j < TN; j++)
                    acc[i][j] = fmaf(a[i], b[j], acc[i][j]);
        }
        __syncthreads();
        Ap += (size_t)BK * HD;
        Bp += (size_t)BK * HD;
    }

    const float inv = g_inv;
    #pragma unroll
    for (int i = 0; i < TM; i++) {
        const int m = m0 + ty * TM + i;
        const size_t base = (size_t)h * Dn * Dn + (size_t)m * Dn + n0 + tx * TN;
        #pragma unroll
        for (int j = 0; j < TN; j += 4) {
            float4 mm = *(const float4*)(Mem + base + j);
            float4 v;
            v.x = mm.x + acc[i][j + 0] * inv;
            v.y = mm.y + acc[i][j + 1] * inv;
            v.z = mm.z + acc[i][j + 2] * inv;
            v.w = mm.w + acc[i][j + 3] * inv;
            *(float4*)(Out + base + j) = v;
        }
    }
}

// ---------------------------------------------------------------------------
// Launch
// ---------------------------------------------------------------------------
extern "C" void kernel_launch(void* const* d_in, const int* in_sizes, int n_in,
                              void* d_out, int out_size) {
    const float* z_query    = (const float*)d_in[0];
    const float* z_state    = (const float*)d_in[1];
    const float* z_value    = (const float*)d_in[2];
    const float* confidence = (const float*)d_in[3];
    const float* Wk         = (const float*)d_in[4];
    const float* Wv         = (const float*)d_in[5];
    const float* Wo         = (const float*)d_in[6];
    const float* memory     = (const float*)d_in[7];

    float* out_vret = (float*)d_out;                         // (B, D)
    float* out_mem  = (float*)d_out + (size_t)Bn * Dn;       // (H, D, D)

    float *pK, *pKw, *pVw, *pVm;
    cudaGetSymbolAddress((void**)&pK,  g_K);
    cudaGetSymbolAddress((void**)&pKw, g_kw);
    cudaGetSymbolAddress((void**)&pVw, g_vw);
    cudaGetSymbolAddress((void**)&pVm, g_vm);
    float* pLam;
    cudaGetSymbolAddress((void**)&pLam, g_lam);

    // 1. lam_m + mask-sum
    prep_kernel<<<1, 256>>>(confidence);

    // 2. K = z_query @ Wk                      (4096 x 8192, K=512)
    sgemm_nn<<<dim3(HD / BN, Bn / BM), 256>>>(z_query, Wk, pK, Bn, HD, Dn, 1.0f, nullptr);

    // 3. vmean = (1/H) * K @ memory.reshape(8192,512)   (4096 x 512, K=8192)
    sgemm_nn<<<dim3(Dn / BN, Bn / BM), 256>>>(pK, memory, pVm, Bn, Dn, HD, 1.0f / Hn, nullptr);

    // 4. v_ret = vmean @ Wo -> d_out           (4096 x 512, K=512)
    sgemm_nn<<<dim3(Dn / BN, Bn / BM), 256>>>(pVm, Wo, out_vret, Bn, Dn, Dn, 1.0f, nullptr);

    // 5. kw_scaled = (z_state @ Wk) * lam_m[row]   (4096 x 8192, K=512)
    sgemm_nn<<<dim3(HD / BN, Bn / BM), 256>>>(z_state, Wk, pKw, Bn, HD, Dn, 1.0f, pLam);

    // 6. vw = z_value @ Wv                     (4096 x 8192, K=512)
    sgemm_nn<<<dim3(HD / BN, Bn / BM), 256>>>(z_value, Wv, pVw, Bn, HD, Dn, 1.0f, nullptr);

    // 7. new_memory = memory + (kw_h^T @ vw_h) * g_inv  per head
    sgemm_atb_delta<<<dim3(Dn / BN, Dn / BM, Hn), 256>>>(pKw, pVw, memory, out_mem);
}